// round 1
// baseline (speedup 1.0000x reference)
#include <cuda_runtime.h>
#include <cuda_bf16.h>
#include <cstdint>

// Problem constants (fixed by setup_inputs)
#define PB 4
#define PN 1024
#define PD 512
#define PH 8
#define PDH 64
#define P3D 1536
#define MROWS 8192           // 4096 x_tan rows + 4096 v_tan rows
#define ZSZ (4ull*1024*512)  // z_tan element count

// ---------------- device scratch (no allocations allowed) ----------------
__device__ float g_qkv[(size_t)MROWS * P3D];      // stacked projection output (50.3 MB)
__device__ float g_cq[PB*PH*PN], g_gq[PB*PH*PN];
__device__ float g_ck[PB*PH*PN], g_gk[PB*PH*PN];
__device__ float g_vqs[PB*PH*PN], g_vks[PB*PH*PN];
__device__ unsigned g_bits1[PN*32], g_bits2[PN*32], g_bits3[PN*32];
__device__ unsigned char g_topo[(size_t)PN*PN];

// ---------------- K1: QKV projection GEMM --------------------------------
// C[m, c] = sum_k A[m,k] * W[c,k] + bias[c];  A = [x_tan ; v_tan] (8192x512)
__global__ __launch_bounds__(256, 2)
void k_gemm_qkv(const float* __restrict__ X, const float* __restrict__ V,
                const float* __restrict__ W, const float* __restrict__ bias) {
    const int bn = blockIdx.x;          // 0..11  (col tile of 128)
    const int bm = blockIdx.y;          // 0..63  (row tile of 128)
    if (bm >= 32 && bn >= 8) return;    // v_tan rows don't need the v_s columns

    __shared__ float As[16][132];
    __shared__ float Bs[16][132];

    const float* A = (bm < 32) ? X : V;
    const int rowBase = (bm & 31) * 128;
    const int colBase = bn * 128;
    const int tid = threadIdx.x;
    const int tx = tid & 15, ty = tid >> 4;

    float c[8][8];
#pragma unroll
    for (int i = 0; i < 8; i++)
#pragma unroll
        for (int j = 0; j < 8; j++) c[i][j] = 0.f;

    const int lr  = tid >> 2;           // 0..63
    const int lk4 = (tid & 3) * 4;      // 0,4,8,12

    for (int k0 = 0; k0 < PD; k0 += 16) {
#pragma unroll
        for (int it = 0; it < 2; ++it) {
            int r = lr + it * 64;
            float4 a4 = *reinterpret_cast<const float4*>(&A[(size_t)(rowBase + r) * PD + k0 + lk4]);
            As[lk4 + 0][r] = a4.x; As[lk4 + 1][r] = a4.y;
            As[lk4 + 2][r] = a4.z; As[lk4 + 3][r] = a4.w;
            float4 b4 = *reinterpret_cast<const float4*>(&W[(size_t)(colBase + r) * PD + k0 + lk4]);
            Bs[lk4 + 0][r] = b4.x; Bs[lk4 + 1][r] = b4.y;
            Bs[lk4 + 2][r] = b4.z; Bs[lk4 + 3][r] = b4.w;
        }
        __syncthreads();
#pragma unroll
        for (int kk = 0; kk < 16; ++kk) {
            float a[8], b[8];
            *(float4*)&a[0] = *(const float4*)&As[kk][ty * 4];
            *(float4*)&a[4] = *(const float4*)&As[kk][64 + ty * 4];
            *(float4*)&b[0] = *(const float4*)&Bs[kk][tx * 4];
            *(float4*)&b[4] = *(const float4*)&Bs[kk][64 + tx * 4];
#pragma unroll
            for (int i = 0; i < 8; i++)
#pragma unroll
                for (int j = 0; j < 8; j++) c[i][j] = fmaf(a[i], b[j], c[i][j]);
        }
        __syncthreads();
    }

#pragma unroll
    for (int ih = 0; ih < 2; ih++)
#pragma unroll
        for (int i = 0; i < 4; i++) {
            int m = bm * 128 + ih * 64 + ty * 4 + i;
            float* outp = g_qkv + (size_t)m * P3D + colBase;
#pragma unroll
            for (int jh = 0; jh < 2; jh++) {
                int cb = jh * 64 + tx * 4;
                float4 v;
                v.x = c[ih * 4 + i][jh * 4 + 0] + bias[colBase + cb + 0];
                v.y = c[ih * 4 + i][jh * 4 + 1] + bias[colBase + cb + 1];
                v.z = c[ih * 4 + i][jh * 4 + 2] + bias[colBase + cb + 2];
                v.w = c[ih * 4 + i][jh * 4 + 3] + bias[colBase + cb + 3];
                *(float4*)&outp[cb] = v;
            }
        }
}

// ---------------- K2: per-token hyperbolic scalars -----------------------
__global__ void k_prep() {
    int gw = (blockIdx.x * blockDim.x + threadIdx.x) >> 5;
    int lane = threadIdx.x & 31;
    if (gw >= 4 * PB * PH * PN) return;
    int kind = gw & 3;          // 0:q_s 1:k_s 2:v_q 3:v_k
    int t = gw >> 2;            // (b*H + h)*N + n
    int b = t >> 13;
    int h = (t >> 10) & 7;
    int n = t & 1023;
    int row = b * PN + n + ((kind >= 2) ? 4096 : 0);
    int comp = kind & 1;
    const float* p = g_qkv + (size_t)row * P3D + comp * PD + h * PDH;
    float x0 = p[lane], x1 = p[lane + 32];
    float ss = x0 * x0 + x1 * x1;
#pragma unroll
    for (int o = 16; o; o >>= 1) ss += __shfl_xor_sync(~0u, ss, o);
    if (lane == 0) {
        if (kind < 2) {
            float norm  = sqrtf(fmaxf(ss, 1e-7f));
            float alpha = fminf(3.0f / norm, 1.0f);
            float n2    = sqrtf(fmaxf(ss * alpha * alpha, 1e-14f));
            float ch    = coshf(n2);
            float g     = (sinhf(n2) / n2) * alpha;
            if (kind == 0) { g_cq[t] = ch; g_gq[t] = g; }
            else           { g_ck[t] = ch; g_gk[t] = g; }
        } else {
            if (kind == 2) g_vqs[t] = ss; else g_vks[t] = ss;
        }
    }
}

// ---------------- K3..K6: topology masks via bitset boolean matmul -------
__global__ void k_pack(const float* __restrict__ topo_bias) {
    int i = blockIdx.x, j = threadIdx.x;
    unsigned m = __ballot_sync(~0u, topo_bias[(size_t)i * PN + j] > 0.0f);
    if ((j & 31) == 0) g_bits1[i * 32 + (j >> 5)] = m;
}
__global__ void k_sq2() {  // bits2 = (A^2 > 0)
    int i = blockIdx.x, lane = threadIdx.x;
    unsigned acc = 0;
    for (int w = 0; w < 32; w++) {
        unsigned aw = g_bits1[i * 32 + w];
        while (aw) {
            int bpos = __ffs(aw) - 1; aw &= aw - 1;
            acc |= g_bits1[(w * 32 + bpos) * 32 + lane];
        }
    }
    g_bits2[i * 32 + lane] = acc;
}
__global__ void k_sq3() {  // bits3 = (A^3 > 0) = (A^2>0) boolean-matmul (A>0)
    int i = blockIdx.x, lane = threadIdx.x;
    unsigned acc = 0;
    for (int w = 0; w < 32; w++) {
        unsigned aw = g_bits2[i * 32 + w];
        while (aw) {
            int bpos = __ffs(aw) - 1; aw &= aw - 1;
            acc |= g_bits1[(w * 32 + bpos) * 32 + lane];
        }
    }
    g_bits3[i * 32 + lane] = acc;
}
__global__ void k_byte() {
    int i = blockIdx.x, j = threadIdx.x;
    int w = j >> 5, bpos = j & 31;
    unsigned char v = 0;
    if (i != j) {
        v = (unsigned char)(((g_bits1[i * 32 + w] >> bpos) & 1) |
                            (((g_bits2[i * 32 + w] >> bpos) & 1) << 1) |
                            (((g_bits3[i * 32 + w] >> bpos) & 1) << 2));
    }
    g_topo[(size_t)i * PN + j] = v;
}

// ---------------- K7: raw score tiles (dual-accumulator GEMM) ------------
__global__ __launch_bounds__(256, 2)
void k_scores(const float* __restrict__ tau, const float* __restrict__ gamma,
              float* __restrict__ attn) {
    __shared__ float Qs[32][68], Ks[32][68], VQ[32][68], VK[32][68];
    __shared__ float lut[8];

    const int bh = blockIdx.z;             // b*H + h
    const int b = bh >> 3, h = bh & 7;
    const int i0 = blockIdx.y * 64;
    const int j0 = blockIdx.x * 64;
    const int tid = threadIdx.x;
    const int tx = tid & 15, ty = tid >> 4;

    if (tid < 8) {
        float g0 = gamma[h * 3 + 0], g1 = gamma[h * 3 + 1], g2 = gamma[h * 3 + 2];
        lut[tid] = g0 * (float)(tid & 1) + g1 * (float)((tid >> 1) & 1) + g2 * (float)((tid >> 2) & 1);
    }

    float qk[4][4], vv[4][4];
#pragma unroll
    for (int a = 0; a < 4; a++)
#pragma unroll
        for (int c2 = 0; c2 < 4; c2++) { qk[a][c2] = 0.f; vv[a][c2] = 0.f; }

    const int lr  = tid >> 2;       // 0..63
    const int lk4 = (tid & 3) * 4;  // 0..12

    for (int dk0 = 0; dk0 < PDH; dk0 += 32) {
        __syncthreads();
#pragma unroll
        for (int half = 0; half < 2; half++) {
            int kk = lk4 + half * 16;
            float4 q4  = *(const float4*)&g_qkv[(size_t)(b * PN + i0 + lr) * P3D + h * PDH + dk0 + kk];
            float4 k4  = *(const float4*)&g_qkv[(size_t)(b * PN + j0 + lr) * P3D + PD + h * PDH + dk0 + kk];
            float4 vq4 = *(const float4*)&g_qkv[(size_t)(4096 + b * PN + i0 + lr) * P3D + h * PDH + dk0 + kk];
            float4 vk4 = *(const float4*)&g_qkv[(size_t)(4096 + b * PN + j0 + lr) * P3D + PD + h * PDH + dk0 + kk];
            Qs[kk + 0][lr] = q4.x; Qs[kk + 1][lr] = q4.y; Qs[kk + 2][lr] = q4.z; Qs[kk + 3][lr] = q4.w;
            Ks[kk + 0][lr] = k4.x; Ks[kk + 1][lr] = k4.y; Ks[kk + 2][lr] = k4.z; Ks[kk + 3][lr] = k4.w;
            VQ[kk + 0][lr] = vq4.x; VQ[kk + 1][lr] = vq4.y; VQ[kk + 2][lr] = vq4.z; VQ[kk + 3][lr] = vq4.w;
            VK[kk + 0][lr] = vk4.x; VK[kk + 1][lr] = vk4.y; VK[kk + 2][lr] = vk4.z; VK[kk + 3][lr] = vk4.w;
        }
        __syncthreads();
#pragma unroll
        for (int kk = 0; kk < 32; kk++) {
            float qa[4], kb[4], va[4], vb[4];
            *(float4*)qa = *(const float4*)&Qs[kk][ty * 4];
            *(float4*)kb = *(const float4*)&Ks[kk][tx * 4];
            *(float4*)va = *(const float4*)&VQ[kk][ty * 4];
            *(float4*)vb = *(const float4*)&VK[kk][tx * 4];
#pragma unroll
            for (int a = 0; a < 4; a++)
#pragma unroll
                for (int c2 = 0; c2 < 4; c2++) {
                    qk[a][c2] = fmaf(qa[a], kb[c2], qk[a][c2]);
                    vv[a][c2] = fmaf(va[a], vb[c2], vv[a][c2]);
                }
        }
    }

    const float invtau = 1.0f / fmaxf(tau[h], 1e-3f);
    const int ib = bh * PN + i0 + ty * 4;
    const int jb = bh * PN + j0 + tx * 4;
    float cqi[4], gqi[4], vqi[4], ckj[4], gkj[4], vkj[4];
#pragma unroll
    for (int a = 0; a < 4; a++) {
        cqi[a] = g_cq[ib + a]; gqi[a] = g_gq[ib + a]; vqi[a] = g_vqs[ib + a];
        ckj[a] = g_ck[jb + a]; gkj[a] = g_gk[jb + a]; vkj[a] = g_vks[jb + a];
    }
#pragma unroll
    for (int a = 0; a < 4; a++) {
        uchar4 tb = *(const uchar4*)&g_topo[(size_t)(i0 + ty * 4 + a) * PN + j0 + tx * 4];
        float4 s;
        s.x = (1.0f + gqi[a] * gkj[0] * qk[a][0] - cqi[a] * ckj[0]) * invtau
              - fmaxf(vqi[a] + vkj[0] - 2.0f * vv[a][0], 0.0f) + lut[tb.x & 7];
        s.y = (1.0f + gqi[a] * gkj[1] * qk[a][1] - cqi[a] * ckj[1]) * invtau
              - fmaxf(vqi[a] + vkj[1] - 2.0f * vv[a][1], 0.0f) + lut[tb.y & 7];
        s.z = (1.0f + gqi[a] * gkj[2] * qk[a][2] - cqi[a] * ckj[2]) * invtau
              - fmaxf(vqi[a] + vkj[2] - 2.0f * vv[a][2], 0.0f) + lut[tb.z & 7];
        s.w = (1.0f + gqi[a] * gkj[3] * qk[a][3] - cqi[a] * ckj[3]) * invtau
              - fmaxf(vqi[a] + vkj[3] - 2.0f * vv[a][3], 0.0f) + lut[tb.w & 7];
        *(float4*)&attn[(size_t)(bh * PN + i0 + ty * 4 + a) * PN + j0 + tx * 4] = s;
    }
}

// ---------------- K8: row softmax (in place) -----------------------------
__global__ __launch_bounds__(256)
void k_softmax(float* __restrict__ attn) {
    __shared__ float red[8];
    const int row = blockIdx.x;
    float* p = attn + (size_t)row * PN;
    const int t = threadIdx.x;
    float4 v = *(float4*)&p[t * 4];
    float m = fmaxf(fmaxf(v.x, v.y), fmaxf(v.z, v.w));
#pragma unroll
    for (int o = 16; o; o >>= 1) m = fmaxf(m, __shfl_xor_sync(~0u, m, o));
    if ((t & 31) == 0) red[t >> 5] = m;
    __syncthreads();
    float mm = red[0];
#pragma unroll
    for (int i = 1; i < 8; i++) mm = fmaxf(mm, red[i]);
    __syncthreads();
    v.x = __expf(v.x - mm); v.y = __expf(v.y - mm);
    v.z = __expf(v.z - mm); v.w = __expf(v.w - mm);
    float s = v.x + v.y + v.z + v.w;
#pragma unroll
    for (int o = 16; o; o >>= 1) s += __shfl_xor_sync(~0u, s, o);
    if ((t & 31) == 0) red[t >> 5] = s;
    __syncthreads();
    float ss = 0.f;
#pragma unroll
    for (int i = 0; i < 8; i++) ss += red[i];
    float inv = 1.0f / ss;
    v.x *= inv; v.y *= inv; v.z *= inv; v.w *= inv;
    *(float4*)&p[t * 4] = v;
}

// ---------------- K9: z = attn @ v_s, scattered to z_tan -----------------
__global__ __launch_bounds__(256, 2)
void k_zgemm(const float* __restrict__ attn, float* __restrict__ zout) {
    __shared__ float As[32][68];  // [k][i]
    __shared__ float Vs[32][68];  // [k][d]
    const int bh = blockIdx.z;
    const int b = bh >> 3, h = bh & 7;
    const int i0 = blockIdx.y * 64;
    const int tid = threadIdx.x;
    const int tx = tid & 15, ty = tid >> 4;

    float c[4][4];
#pragma unroll
    for (int a = 0; a < 4; a++)
#pragma unroll
        for (int j = 0; j < 4; j++) c[a][j] = 0.f;

    const int lr  = tid >> 2;        // 0..63 (attn rows)
    const int lk4 = (tid & 3) * 4;
    const int vr  = tid >> 3;        // 0..31 (v_s k-rows)
    const int vd  = (tid & 7) * 4;

    for (int k0 = 0; k0 < PN; k0 += 32) {
        __syncthreads();
#pragma unroll
        for (int half = 0; half < 2; half++) {
            int kk = lk4 + half * 16;
            float4 a4 = *(const float4*)&attn[(size_t)(bh * PN + i0 + lr) * PN + k0 + kk];
            As[kk + 0][lr] = a4.x; As[kk + 1][lr] = a4.y;
            As[kk + 2][lr] = a4.z; As[kk + 3][lr] = a4.w;
            int dd = vd + half * 32;
            float4 v4 = *(const float4*)&g_qkv[(size_t)(b * PN + k0 + vr) * P3D + 2 * PD + h * PDH + dd];
            *(float4*)&Vs[vr][dd] = v4;
        }
        __syncthreads();
#pragma unroll
        for (int kk = 0; kk < 32; kk++) {
            float a4[4], v4[4];
            *(float4*)a4 = *(const float4*)&As[kk][ty * 4];
            *(float4*)v4 = *(const float4*)&Vs[kk][tx * 4];
#pragma unroll
            for (int a = 0; a < 4; a++)
#pragma unroll
                for (int j = 0; j < 4; j++) c[a][j] = fmaf(a4[a], v4[j], c[a][j]);
        }
    }
#pragma unroll
    for (int a = 0; a < 4; a++) {
        float4 v; v.x = c[a][0]; v.y = c[a][1]; v.z = c[a][2]; v.w = c[a][3];
        *(float4*)&zout[(size_t)(b * PN + i0 + ty * 4 + a) * PD + h * PDH + tx * 4] = v;
    }
}

// ---------------- launch ---------------------------------------------------
extern "C" void kernel_launch(void* const* d_in, const int* in_sizes, int n_in,
                              void* d_out, int out_size) {
    const float* x     = (const float*)d_in[0];
    const float* v     = (const float*)d_in[1];
    const float* topo  = (const float*)d_in[2];
    const float* w     = (const float*)d_in[3];
    const float* bias  = (const float*)d_in[4];
    const float* tau   = (const float*)d_in[5];
    const float* gamma = (const float*)d_in[6];

    float* out  = (float*)d_out;
    float* z    = out;          // (B, N, D)
    float* attn = out + ZSZ;    // (B, H, N, N), also used as raw-score scratch

    k_gemm_qkv<<<dim3(12, 64), 256>>>(x, v, w, bias);
    k_prep<<<16384, 256>>>();
    k_pack<<<PN, PN>>>(topo);
    k_sq2<<<PN, 32>>>();
    k_sq3<<<PN, 32>>>();
    k_byte<<<PN, PN>>>();
    k_scores<<<dim3(16, 16, 32), 256>>>(tau, gamma, attn);
    k_softmax<<<PB * PH * PN, 256>>>(attn);
    k_zgemm<<<dim3(1, 16, 32), 256>>>(attn, z);
}

// round 4
// speedup vs baseline: 1.1028x; 1.1028x over previous
#include <cuda_runtime.h>
#include <cuda_bf16.h>
#include <mma.h>
#include <cstdint>

using namespace nvcuda;

#define PB 4
#define PN 1024
#define PD 512
#define PH 8
#define PDH 64
#define P3D 1536
#define NBH 32
#define ZSZ (4ull*1024*512)

// ---------------- device scratch (no allocations allowed) ----------------
__device__ float g_qkv[(size_t)8192 * P3D];              // fp32 projection out (no bias)
__device__ __nv_bfloat16 g_pa[(size_t)8192 * 1024];      // [x;v] rows: [hi512|lo512]
__device__ __nv_bfloat16 g_pw[(size_t)1536 * 1024];      // W rows:    [hi512|lo512]
__device__ __nv_bfloat16 g_sq[(size_t)NBH*PN*128];       // scaled q rows [hi64|lo64]
__device__ __nv_bfloat16 g_sk[(size_t)NBH*PN*128];
__device__ __nv_bfloat16 g_svq[(size_t)NBH*PN*128];
__device__ __nv_bfloat16 g_svk[(size_t)NBH*PN*128];
__device__ __nv_bfloat16 g_asp[(size_t)NBH*PN*2048];     // attn rows [hi1024|lo1024]
__device__ __nv_bfloat16 g_vz[(size_t)NBH*PDH*2048];     // v_s^T rows [hi1024|lo1024]
__device__ float g_cq[NBH*PN], g_ck[NBH*PN], g_vqs[NBH*PN], g_vks[NBH*PN];
__device__ unsigned g_bits1[PN*32], g_bits2[PN*32], g_bits3[PN*32];
__device__ unsigned char g_topo[(size_t)PN*PN];

typedef wmma::fragment<wmma::matrix_a, 16, 16, 16, __nv_bfloat16, wmma::row_major> FragA;
typedef wmma::fragment<wmma::matrix_b, 16, 16, 16, __nv_bfloat16, wmma::col_major> FragB;
typedef wmma::fragment<wmma::accumulator, 16, 16, 16, float> FragC;

// ---------------- split conversions ----------------
__global__ __launch_bounds__(256) void k_cvt_pa(const float* __restrict__ X,
                                                const float* __restrict__ V) {
    size_t i = (size_t)blockIdx.x * 256 + threadIdx.x;     // 8192*512
    int r = (int)(i >> 9), k = (int)(i & 511);
    float val = (r < 4096) ? X[i] : V[i - (size_t)4096 * 512];
    __nv_bfloat16 hb = __float2bfloat16(val);
    __nv_bfloat16 lb = __float2bfloat16(val - __bfloat162float(hb));
    g_pa[(size_t)r * 1024 + k] = hb;
    g_pa[(size_t)r * 1024 + 512 + k] = lb;
}
__global__ __launch_bounds__(256) void k_cvt_pw(const float* __restrict__ W) {
    size_t i = (size_t)blockIdx.x * 256 + threadIdx.x;     // 1536*512
    int r = (int)(i >> 9), k = (int)(i & 511);
    float val = W[i];
    __nv_bfloat16 hb = __float2bfloat16(val);
    __nv_bfloat16 lb = __float2bfloat16(val - __bfloat162float(hb));
    g_pw[(size_t)r * 1024 + k] = hb;
    g_pw[(size_t)r * 1024 + 512 + k] = lb;
}

// ---------------- T1: projection GEMM (WMMA bf16 3-term) -----------------
// g_qkv[m, c] = sum_k A[m,k]*W[c,k]    (bias folded into consumers)
__global__ __launch_bounds__(256)
void t_proj() {
    __shared__ __nv_bfloat16 Ah[128][40], Al[128][40], Bh[128][40], Bl[128][40];
    const int bn = blockIdx.x, bm = blockIdx.y;
    if (bm >= 32 && bn >= 8) return;          // v rows don't need v_s cols
    const int m0 = bm * 128, c0 = bn * 128;
    const int tid = threadIdx.x;
    const int wid = tid >> 5;
    const int wm = wid >> 2, wn = wid & 3;    // warp tile: 64 x 32

    FragC acc[4][2];
#pragma unroll
    for (int i = 0; i < 4; i++)
#pragma unroll
        for (int j = 0; j < 2; j++) wmma::fill_fragment(acc[i][j], 0.0f);

    for (int k0 = 0; k0 < 512; k0 += 32) {
#pragma unroll
        for (int t = 0; t < 2; t++) {
            int u = tid + t * 256;            // 512 uint4 per buffer
            int r = u >> 2, c8 = (u & 3) * 8;
            *(uint4*)&Ah[r][c8] = *(const uint4*)&g_pa[(size_t)(m0 + r) * 1024 + k0 + c8];
            *(uint4*)&Al[r][c8] = *(const uint4*)&g_pa[(size_t)(m0 + r) * 1024 + 512 + k0 + c8];
            *(uint4*)&Bh[r][c8] = *(const uint4*)&g_pw[(size_t)(c0 + r) * 1024 + k0 + c8];
            *(uint4*)&Bl[r][c8] = *(const uint4*)&g_pw[(size_t)(c0 + r) * 1024 + 512 + k0 + c8];
        }
        __syncthreads();
#pragma unroll
        for (int kk = 0; kk < 32; kk += 16) {
            FragB fbh[2], fbl[2];
#pragma unroll
            for (int j = 0; j < 2; j++) {
                wmma::load_matrix_sync(fbh[j], &Bh[wn * 32 + j * 16][kk], 40);
                wmma::load_matrix_sync(fbl[j], &Bl[wn * 32 + j * 16][kk], 40);
            }
#pragma unroll
            for (int i = 0; i < 4; i++) {
                FragA fah, fal;
                wmma::load_matrix_sync(fah, &Ah[wm * 64 + i * 16][kk], 40);
                wmma::load_matrix_sync(fal, &Al[wm * 64 + i * 16][kk], 40);
#pragma unroll
                for (int j = 0; j < 2; j++) {
                    wmma::mma_sync(acc[i][j], fah, fbh[j], acc[i][j]);
                    wmma::mma_sync(acc[i][j], fal, fbh[j], acc[i][j]);
                    wmma::mma_sync(acc[i][j], fah, fbl[j], acc[i][j]);
                }
            }
        }
        __syncthreads();
    }
#pragma unroll
    for (int i = 0; i < 4; i++)
#pragma unroll
        for (int j = 0; j < 2; j++)
            wmma::store_matrix_sync(
                &g_qkv[(size_t)(m0 + wm * 64 + i * 16) * P3D + c0 + wn * 32 + j * 16],
                acc[i][j], P3D, wmma::mem_row_major);
}

// ---------------- prep: scalars + scaled operand split (adds bias) -------
__global__ __launch_bounds__(128) void k_prep2(const float* __restrict__ bias) {
    int gw = (blockIdx.x * 128 + threadIdx.x) >> 5;
    int lane = threadIdx.x & 31;
    int kind = gw & 3;          // 0:q 1:k 2:vq 3:vk
    int t = gw >> 2;            // (b*8+h)*1024 + n
    int b = t >> 13, h = (t >> 10) & 7, n = t & 1023;
    int row = b * PN + n + ((kind >= 2) ? 4096 : 0);
    int col = ((kind & 1) ? PD : 0) + h * PDH;
    const float* p = g_qkv + (size_t)row * P3D + col;
    float x0 = p[lane] + bias[col + lane];
    float x1 = p[lane + 32] + bias[col + lane + 32];
    float ss = x0 * x0 + x1 * x1;
#pragma unroll
    for (int o = 16; o; o >>= 1) ss += __shfl_xor_sync(~0u, ss, o);
    float scale = 1.0f;
    if (kind < 2) {
        float norm  = sqrtf(fmaxf(ss, 1e-7f));
        float alpha = fminf(3.0f / norm, 1.0f);
        float n2    = sqrtf(fmaxf(ss * alpha * alpha, 1e-14f));
        scale = (sinhf(n2) / n2) * alpha;
        if (lane == 0) { if (kind == 0) g_cq[t] = coshf(n2); else g_ck[t] = coshf(n2); }
    } else {
        if (lane == 0) { if (kind == 2) g_vqs[t] = ss; else g_vks[t] = ss; }
    }
    float s0 = scale * x0, s1 = scale * x1;
    __nv_bfloat16 h0 = __float2bfloat16(s0), h1 = __float2bfloat16(s1);
    __nv_bfloat16 l0 = __float2bfloat16(s0 - __bfloat162float(h0));
    __nv_bfloat16 l1 = __float2bfloat16(s1 - __bfloat162float(h1));
    __nv_bfloat16* out = (kind == 0 ? g_sq : kind == 1 ? g_sk : kind == 2 ? g_svq : g_svk)
                         + (size_t)t * 128;
    out[lane] = h0; out[32 + lane] = h1; out[64 + lane] = l0; out[96 + lane] = l1;
}

// ---------------- v_s transpose + split (adds bias) ----------------
__global__ __launch_bounds__(256) void k_vhat(const float* __restrict__ bias) {
    __shared__ float tile[64][65];
    const int bh = blockIdx.y, j0 = blockIdx.x * 64;
    const int b = bh >> 3, h = bh & 7;
    const int tid = threadIdx.x;
#pragma unroll
    for (int i = 0; i < 4; i++) {
        int lin = tid + i * 256;
        int r = lin >> 4, c4 = (lin & 15) * 4;
        int col = 1024 + h * PDH + c4;
        float4 v = *reinterpret_cast<const float4*>(
            &g_qkv[(size_t)(b * PN + j0 + r) * P3D + col]);
        tile[r][c4]   = v.x + bias[col];
        tile[r][c4+1] = v.y + bias[col+1];
        tile[r][c4+2] = v.z + bias[col+2];
        tile[r][c4+3] = v.w + bias[col+3];
    }
    __syncthreads();
#pragma unroll
    for (int i = 0; i < 4; i++) {
        int lin = tid + i * 256;
        int d = lin >> 4, jq = (lin & 15) * 4;
        __nv_bfloat16* out = g_vz + (size_t)(bh * PDH + d) * 2048 + j0 + jq;
        unsigned hs[4], ls[4];
#pragma unroll
        for (int k = 0; k < 4; k++) {
            float x = tile[jq + k][d];
            __nv_bfloat16 hb = __float2bfloat16(x);
            __nv_bfloat16 lb = __float2bfloat16(x - __bfloat162float(hb));
            hs[k] = (unsigned)__bfloat16_as_ushort(hb);
            ls[k] = (unsigned)__bfloat16_as_ushort(lb);
        }
        uint2 hh; hh.x = hs[0] | (hs[1] << 16); hh.y = hs[2] | (hs[3] << 16);
        uint2 ll; ll.x = ls[0] | (ls[1] << 16); ll.y = ls[2] | (ls[3] << 16);
        *reinterpret_cast<uint2*>(out) = hh;
        *reinterpret_cast<uint2*>(out + 1024) = ll;
    }
}

// ---------------- topology: boolean bitset powers ----------------
__global__ void k_pack(const float* __restrict__ topo_bias) {
    int i = blockIdx.x, j = threadIdx.x;
    unsigned m = __ballot_sync(~0u, topo_bias[(size_t)i * PN + j] > 0.0f);
    if ((j & 31) == 0) g_bits1[i * 32 + (j >> 5)] = m;
}
__global__ __launch_bounds__(256) void k_sq2() {
    int i = blockIdx.x * 8 + (threadIdx.x >> 5), lane = threadIdx.x & 31;
    unsigned acc = 0;
    for (int w = 0; w < 32; w++) {
        unsigned aw = g_bits1[i * 32 + w];
        while (aw) { int bp = __ffs(aw) - 1; aw &= aw - 1; acc |= g_bits1[(w*32+bp)*32 + lane]; }
    }
    g_bits2[i * 32 + lane] = acc;
}
__global__ __launch_bounds__(256) void k_sq3() {
    int i = blockIdx.x * 8 + (threadIdx.x >> 5), lane = threadIdx.x & 31;
    unsigned acc = 0;
    for (int w = 0; w < 32; w++) {
        unsigned aw = g_bits2[i * 32 + w];
        while (aw) { int bp = __ffs(aw) - 1; aw &= aw - 1; acc |= g_bits1[(w*32+bp)*32 + lane]; }
    }
    g_bits3[i * 32 + lane] = acc;
}
__global__ void k_byte() {
    int i = blockIdx.x, j = threadIdx.x;
    int w = j >> 5, bp = j & 31;
    unsigned char v = 0;
    if (i != j)
        v = (unsigned char)(((g_bits1[i*32+w] >> bp) & 1) |
                            (((g_bits2[i*32+w] >> bp) & 1) << 1) |
                            (((g_bits3[i*32+w] >> bp) & 1) << 2));
    g_topo[(size_t)i * PN + j] = v;
}

// ---------------- T2: score GEMMs + fused epilogue -----------------------
// CTA tile 64(i) x 128(j); phases QK then VV; epilogue via smem round-trip.
__global__ __launch_bounds__(256)
void t_scores(const float* __restrict__ tau, const float* __restrict__ gamma,
              float* __restrict__ attn) {
    extern __shared__ char dsm[];
    __nv_bfloat16 (*As)[136] = (__nv_bfloat16(*)[136])dsm;             // 64 x 136
    __nv_bfloat16 (*Bs)[136] = (__nv_bfloat16(*)[136])(dsm + 17408);   // 128 x 136
    float (*Sqk)[132] = (float(*)[132])dsm;                            // 64 x 132
    float (*Svv)[132] = (float(*)[132])(dsm + 33792);                  // 64 x 132
    __shared__ float s_lut[8];

    const int j0 = blockIdx.x * 128, i0 = blockIdx.y * 64, bh = blockIdx.z;
    const int h = bh & 7;
    const int tid = threadIdx.x;
    const int wid = tid >> 5;
    const int wm = wid >> 2, wn = wid & 3;    // warp tile 32 x 32

    if (tid < 8) {
        float g0 = gamma[h*3+0], g1 = gamma[h*3+1], g2 = gamma[h*3+2];
        s_lut[tid] = g0 * (float)(tid & 1) + g1 * (float)((tid >> 1) & 1)
                   + g2 * (float)((tid >> 2) & 1);
    }

    FragC qk[2][2], vv[2][2];
#pragma unroll
    for (int i = 0; i < 2; i++)
#pragma unroll
        for (int j = 0; j < 2; j++) { wmma::fill_fragment(qk[i][j], 0.f); wmma::fill_fragment(vv[i][j], 0.f); }

#pragma unroll 1
    for (int ph = 0; ph < 2; ph++) {
        const __nv_bfloat16* asrc = (ph == 0 ? g_sq : g_svq) + (size_t)(bh * PN + i0) * 128;
        const __nv_bfloat16* bsrc = (ph == 0 ? g_sk : g_svk) + (size_t)(bh * PN + j0) * 128;
#pragma unroll
        for (int t = 0; t < 4; t++) {         // A: 1024 uint4
            int u = tid + t * 256;
            int r = u >> 4, c8 = (u & 15) * 8;
            *(uint4*)&As[r][c8] = *(const uint4*)&asrc[(size_t)r * 128 + c8];
        }
#pragma unroll
        for (int t = 0; t < 8; t++) {         // B: 2048 uint4
            int u = tid + t * 256;
            int r = u >> 4, c8 = (u & 15) * 8;
            *(uint4*)&Bs[r][c8] = *(const uint4*)&bsrc[(size_t)r * 128 + c8];
        }
        __syncthreads();
        FragC (*acc)[2] = (ph == 0) ? qk : vv;
#pragma unroll
        for (int kk = 0; kk < 64; kk += 16) {
            FragB fbh[2], fbl[2];
#pragma unroll
            for (int j = 0; j < 2; j++) {
                wmma::load_matrix_sync(fbh[j], &Bs[wn * 32 + j * 16][kk], 136);
                wmma::load_matrix_sync(fbl[j], &Bs[wn * 32 + j * 16][64 + kk], 136);
            }
#pragma unroll
            for (int i = 0; i < 2; i++) {
                FragA fah, fal;
                wmma::load_matrix_sync(fah, &As[wm * 32 + i * 16][kk], 136);
                wmma::load_matrix_sync(fal, &As[wm * 32 + i * 16][64 + kk], 136);
#pragma unroll
                for (int j = 0; j < 2; j++) {
                    wmma::mma_sync(acc[i][j], fah, fbh[j], acc[i][j]);
                    wmma::mma_sync(acc[i][j], fal, fbh[j], acc[i][j]);
                    wmma::mma_sync(acc[i][j], fah, fbl[j], acc[i][j]);
                }
            }
        }
        __syncthreads();
    }

    // dump accumulators to smem for coordinate-addressable epilogue
#pragma unroll
    for (int i = 0; i < 2; i++)
#pragma unroll
        for (int j = 0; j < 2; j++) {
            wmma::store_matrix_sync(&Sqk[wm * 32 + i * 16][wn * 32 + j * 16], qk[i][j], 132, wmma::mem_row_major);
            wmma::store_matrix_sync(&Svv[wm * 32 + i * 16][wn * 32 + j * 16], vv[i][j], 132, wmma::mem_row_major);
        }
    __syncthreads();

    const int r = tid >> 2;               // 0..63
    const int ce = (tid & 3) * 32;        // 0..96
    const int i = i0 + r;
    const float invtau = 1.0f / fmaxf(tau[h], 1e-3f);
    const float cqi = g_cq[bh * PN + i], vqi = g_vqs[bh * PN + i];
    float* op = attn + (size_t)(bh * PN + i) * PN + j0;
#pragma unroll
    for (int c = ce; c < ce + 32; c += 4) {
        float4 q4 = *(float4*)&Sqk[r][c];
        float4 w4 = *(float4*)&Svv[r][c];
        float4 ck4 = *(const float4*)&g_ck[bh * PN + j0 + c];
        float4 vk4 = *(const float4*)&g_vks[bh * PN + j0 + c];
        uchar4 tb = *(const uchar4*)&g_topo[(size_t)i * PN + j0 + c];
        float4 s;
        s.x = (1.f + q4.x - cqi * ck4.x) * invtau - fmaxf(vqi + vk4.x - 2.f * w4.x, 0.f) + s_lut[tb.x & 7];
        s.y = (1.f + q4.y - cqi * ck4.y) * invtau - fmaxf(vqi + vk4.y - 2.f * w4.y, 0.f) + s_lut[tb.y & 7];
        s.z = (1.f + q4.z - cqi * ck4.z) * invtau - fmaxf(vqi + vk4.z - 2.f * w4.z, 0.f) + s_lut[tb.z & 7];
        s.w = (1.f + q4.w - cqi * ck4.w) * invtau - fmaxf(vqi + vk4.w - 2.f * w4.w, 0.f) + s_lut[tb.w & 7];
        *(float4*)&op[c] = s;
    }
}

// ---------------- softmax + attn hi/lo split ----------------
__global__ __launch_bounds__(256)
void k_softmax_split(float* __restrict__ attn) {
    __shared__ float red[8];
    const size_t row = blockIdx.x;
    float* p = attn + row * PN;
    const int t = threadIdx.x;
    float4 v = *reinterpret_cast<float4*>(&p[t * 4]);
    float m = fmaxf(fmaxf(v.x, v.y), fmaxf(v.z, v.w));
#pragma unroll
    for (int o = 16; o; o >>= 1) m = fmaxf(m, __shfl_xor_sync(~0u, m, o));
    if ((t & 31) == 0) red[t >> 5] = m;
    __syncthreads();
    float mm = red[0];
#pragma unroll
    for (int i = 1; i < 8; i++) mm = fmaxf(mm, red[i]);
    __syncthreads();
    v.x = __expf(v.x - mm); v.y = __expf(v.y - mm);
    v.z = __expf(v.z - mm); v.w = __expf(v.w - mm);
    float s = v.x + v.y + v.z + v.w;
#pragma unroll
    for (int o = 16; o; o >>= 1) s += __shfl_xor_sync(~0u, s, o);
    if ((t & 31) == 0) red[t >> 5] = s;
    __syncthreads();
    float ss = 0.f;
#pragma unroll
    for (int i = 0; i < 8; i++) ss += red[i];
    float inv = 1.0f / ss;
    v.x *= inv; v.y *= inv; v.z *= inv; v.w *= inv;
    *reinterpret_cast<float4*>(&p[t * 4]) = v;
    float vv[4] = {v.x, v.y, v.z, v.w};
    unsigned hs[4], ls[4];
#pragma unroll
    for (int k = 0; k < 4; k++) {
        __nv_bfloat16 hb = __float2bfloat16(vv[k]);
        __nv_bfloat16 lb = __float2bfloat16(vv[k] - __bfloat162float(hb));
        hs[k] = (unsigned)__bfloat16_as_ushort(hb);
        ls[k] = (unsigned)__bfloat16_as_ushort(lb);
    }
    uint2 hh; hh.x = hs[0] | (hs[1] << 16); hh.y = hs[2] | (hs[3] << 16);
    uint2 ll; ll.x = ls[0] | (ls[1] << 16); ll.y = ls[2] | (ls[3] << 16);
    __nv_bfloat16* o = g_asp + row * 2048 + t * 4;
    *reinterpret_cast<uint2*>(o) = hh;
    *reinterpret_cast<uint2*>(o + 1024) = ll;
}

// ---------------- T3: z = attn @ v_s (WMMA bf16 3-term) ------------------
__global__ __launch_bounds__(256)
void t_zgemm(float* __restrict__ zout) {
    __shared__ __nv_bfloat16 Ah[128][40], Al[128][40], Bh[64][40], Bl[64][40];
    const int i0 = blockIdx.x * 128, bh = blockIdx.y;
    const int b = bh >> 3, h = bh & 7;
    const int tid = threadIdx.x;
    const int wid = tid >> 5;
    const int wm = wid >> 1, wn = wid & 1;    // warp tile 32 x 32

    FragC acc[2][2];
#pragma unroll
    for (int i = 0; i < 2; i++)
#pragma unroll
        for (int j = 0; j < 2; j++) wmma::fill_fragment(acc[i][j], 0.f);

    const __nv_bfloat16* abase = g_asp + (size_t)(bh * PN + i0) * 2048;
    const __nv_bfloat16* bbase = g_vz + (size_t)(bh * PDH) * 2048;

    for (int k0 = 0; k0 < 1024; k0 += 32) {
#pragma unroll
        for (int t = 0; t < 2; t++) {         // A: 512 uint4 per buffer
            int u = tid + t * 256;
            int r = u >> 2, c8 = (u & 3) * 8;
            *(uint4*)&Ah[r][c8] = *(const uint4*)&abase[(size_t)r * 2048 + k0 + c8];
            *(uint4*)&Al[r][c8] = *(const uint4*)&abase[(size_t)r * 2048 + 1024 + k0 + c8];
        }
        {
            int r = tid >> 2, c8 = (tid & 3) * 8;   // B: 256 uint4 per buffer
            *(uint4*)&Bh[r][c8] = *(const uint4*)&bbase[(size_t)r * 2048 + k0 + c8];
            *(uint4*)&Bl[r][c8] = *(const uint4*)&bbase[(size_t)r * 2048 + 1024 + k0 + c8];
        }
        __syncthreads();
#pragma unroll
        for (int kk = 0; kk < 32; kk += 16) {
            FragB fbh[2], fbl[2];
#pragma unroll
            for (int j = 0; j < 2; j++) {
                wmma::load_matrix_sync(fbh[j], &Bh[wn * 32 + j * 16][kk], 40);
                wmma::load_matrix_sync(fbl[j], &Bl[wn * 32 + j * 16][kk], 40);
            }
#pragma unroll
            for (int i = 0; i < 2; i++) {
                FragA fah, fal;
                wmma::load_matrix_sync(fah, &Ah[wm * 32 + i * 16][kk], 40);
                wmma::load_matrix_sync(fal, &Al[wm * 32 + i * 16][kk], 40);
#pragma unroll
                for (int j = 0; j < 2; j++) {
                    wmma::mma_sync(acc[i][j], fah, fbh[j], acc[i][j]);
                    wmma::mma_sync(acc[i][j], fal, fbh[j], acc[i][j]);
                    wmma::mma_sync(acc[i][j], fah, fbl[j], acc[i][j]);
                }
            }
        }
        __syncthreads();
    }
#pragma unroll
    for (int i = 0; i < 2; i++)
#pragma unroll
        for (int j = 0; j < 2; j++)
            wmma::store_matrix_sync(
                &zout[(size_t)(b * PN + i0 + wm * 32 + i * 16) * PD + h * PDH + wn * 32 + j * 16],
                acc[i][j], PD, wmma::mem_row_major);
}

// ---------------- launch ----------------
extern "C" void kernel_launch(void* const* d_in, const int* in_sizes, int n_in,
                              void* d_out, int out_size) {
    const float* x     = (const float*)d_in[0];
    const float* v     = (const float*)d_in[1];
    const float* topo  = (const float*)d_in[2];
    const float* w     = (const float*)d_in[3];
    const float* bias  = (const float*)d_in[4];
    const float* tau   = (const float*)d_in[5];
    const float* gamma = (const float*)d_in[6];

    float* out  = (float*)d_out;
    float* z    = out;
    float* attn = out + ZSZ;

    cudaFuncSetAttribute(t_scores, cudaFuncAttributeMaxDynamicSharedMemorySize, 69632);

    k_cvt_pa<<<16384, 256>>>(x, v);
    k_cvt_pw<<<3072, 256>>>(w);
    t_proj<<<dim3(12, 64), 256>>>();
    k_prep2<<<32768, 128>>>(bias);
    k_vhat<<<dim3(16, 32), 256>>>(bias);
    k_pack<<<PN, PN>>>(topo);
    k_sq2<<<128, 256>>>();
    k_sq3<<<128, 256>>>();
    k_byte<<<PN, PN>>>();
    t_scores<<<dim3(8, 16, 32), 256, 69632>>>(tau, gamma, attn);
    k_softmax_split<<<PB * PH * PN, 256>>>(attn);
    t_zgemm<<<dim3(8, 32), 256>>>(z);
}

// round 5
// speedup vs baseline: 1.4056x; 1.2746x over previous
#include <cuda_runtime.h>
#include <cuda_bf16.h>
#include <mma.h>
#include <cstdint>

using namespace nvcuda;

#define PB 4
#define PN 1024
#define PD 512
#define PH 8
#define PDH 64
#define P3D 1536
#define NBH 32
#define ZSZ (4ull*1024*512)

// ---------------- device scratch (no allocations allowed) ----------------
__device__ float g_qkv[(size_t)8192 * P3D];              // fp32 projection out (no bias)
__device__ __nv_bfloat16 g_pa[(size_t)8192 * 1024];      // [x;v] rows: [hi512|lo512]
__device__ __nv_bfloat16 g_pw[(size_t)1536 * 1024];      // W rows:    [hi512|lo512]
__device__ __nv_bfloat16 g_sa[(size_t)NBH*PN*256];       // A rows: [qh64|vqh64|ql64|vql64]
__device__ __nv_bfloat16 g_sb[(size_t)NBH*PN*256];       // B rows: [kh64|vkh64|kl64|vkl64]
__device__ __nv_bfloat16 g_asp[(size_t)NBH*PN*2048];     // attn rows [hi1024|lo1024]
__device__ __nv_bfloat16 g_vz[(size_t)NBH*PDH*2048];     // v_s^T rows [hi1024|lo1024]
__device__ float g_cq[NBH*PN], g_ck[NBH*PN], g_vqs[NBH*PN], g_vks[NBH*PN];
__device__ unsigned g_bits1[PN*32], g_bits2[PN*32], g_bits3[PN*32];
__device__ unsigned char g_topo[(size_t)PN*PN];

typedef wmma::fragment<wmma::matrix_a, 16, 16, 16, __nv_bfloat16, wmma::row_major> FragA;
typedef wmma::fragment<wmma::matrix_b, 16, 16, 16, __nv_bfloat16, wmma::col_major> FragB;
typedef wmma::fragment<wmma::accumulator, 16, 16, 16, float> FragC;

__device__ __forceinline__ void cpa16(void* sm, const void* g) {
    uint32_t s = (uint32_t)__cvta_generic_to_shared(sm);
    asm volatile("cp.async.cg.shared.global [%0], [%1], 16;" :: "r"(s), "l"(g));
}
#define CP_COMMIT() asm volatile("cp.async.commit_group;" ::: "memory")
#define CP_WAIT1()  asm volatile("cp.async.wait_group 1;" ::: "memory")
#define CP_WAIT0()  asm volatile("cp.async.wait_group 0;" ::: "memory")

// ---------------- split conversions ----------------
__global__ __launch_bounds__(256) void k_cvt_pa(const float* __restrict__ X,
                                                const float* __restrict__ V) {
    size_t i = (size_t)blockIdx.x * 256 + threadIdx.x;     // 8192*512
    int r = (int)(i >> 9), k = (int)(i & 511);
    float val = (r < 4096) ? X[i] : V[i - (size_t)4096 * 512];
    __nv_bfloat16 hb = __float2bfloat16(val);
    __nv_bfloat16 lb = __float2bfloat16(val - __bfloat162float(hb));
    g_pa[(size_t)r * 1024 + k] = hb;
    g_pa[(size_t)r * 1024 + 512 + k] = lb;
}
__global__ __launch_bounds__(256) void k_cvt_pw(const float* __restrict__ W) {
    size_t i = (size_t)blockIdx.x * 256 + threadIdx.x;     // 1536*512
    int r = (int)(i >> 9), k = (int)(i & 511);
    float val = W[i];
    __nv_bfloat16 hb = __float2bfloat16(val);
    __nv_bfloat16 lb = __float2bfloat16(val - __bfloat162float(hb));
    g_pw[(size_t)r * 1024 + k] = hb;
    g_pw[(size_t)r * 1024 + 512 + k] = lb;
}

// ---------------- T1: projection GEMM (pipelined, 3-term bf16) -----------
__global__ __launch_bounds__(256)
void t_proj() {
    extern __shared__ __align__(16) uint8_t dsm[];
    const int bn = blockIdx.x, bm = blockIdx.y;
    if (bm >= 32 && bn >= 8) return;          // v rows don't need v_s cols
    const int m0 = bm * 128, c0 = bn * 128;
    const int tid = threadIdx.x;
    const int wid = tid >> 5;
    const int wm = wid >> 2, wn = wid & 3;    // warp tile 64 x 32

    FragC acc[4][2];
#pragma unroll
    for (int i = 0; i < 4; i++)
#pragma unroll
        for (int j = 0; j < 2; j++) wmma::fill_fragment(acc[i][j], 0.0f);

    auto sbuf = [&](int st, int w) -> __nv_bfloat16* {
        return (__nv_bfloat16*)(dsm + st * 40960 + w * 10240);
    };
    auto loadstage = [&](int st, int k0) {
        __nv_bfloat16 *Ah = sbuf(st, 0), *Al = sbuf(st, 1), *Bh = sbuf(st, 2), *Bl = sbuf(st, 3);
#pragma unroll
        for (int t = 0; t < 2; t++) {
            int u = tid + t * 256;            // 512 uint4 per buffer
            int r = u >> 2, c8 = (u & 3) * 8;
            cpa16(&Ah[r * 40 + c8], &g_pa[(size_t)(m0 + r) * 1024 + k0 + c8]);
            cpa16(&Al[r * 40 + c8], &g_pa[(size_t)(m0 + r) * 1024 + 512 + k0 + c8]);
            cpa16(&Bh[r * 40 + c8], &g_pw[(size_t)(c0 + r) * 1024 + k0 + c8]);
            cpa16(&Bl[r * 40 + c8], &g_pw[(size_t)(c0 + r) * 1024 + 512 + k0 + c8]);
        }
    };

    loadstage(0, 0); CP_COMMIT();
#pragma unroll 1
    for (int ch = 0; ch < 16; ++ch) {
        if (ch < 15) { loadstage((ch + 1) & 1, (ch + 1) * 32); CP_COMMIT(); CP_WAIT1(); }
        else CP_WAIT0();
        __syncthreads();
        __nv_bfloat16 *Ah = sbuf(ch & 1, 0), *Al = sbuf(ch & 1, 1),
                      *Bh = sbuf(ch & 1, 2), *Bl = sbuf(ch & 1, 3);
#pragma unroll
        for (int kk = 0; kk < 32; kk += 16) {
            FragB fbh[2], fbl[2];
#pragma unroll
            for (int j = 0; j < 2; j++) {
                wmma::load_matrix_sync(fbh[j], &Bh[(wn * 32 + j * 16) * 40 + kk], 40);
                wmma::load_matrix_sync(fbl[j], &Bl[(wn * 32 + j * 16) * 40 + kk], 40);
            }
#pragma unroll
            for (int i = 0; i < 4; i++) {
                FragA fah, fal;
                wmma::load_matrix_sync(fah, &Ah[(wm * 64 + i * 16) * 40 + kk], 40);
                wmma::load_matrix_sync(fal, &Al[(wm * 64 + i * 16) * 40 + kk], 40);
#pragma unroll
                for (int j = 0; j < 2; j++) {
                    wmma::mma_sync(acc[i][j], fah, fbh[j], acc[i][j]);
                    wmma::mma_sync(acc[i][j], fal, fbh[j], acc[i][j]);
                    wmma::mma_sync(acc[i][j], fah, fbl[j], acc[i][j]);
                }
            }
        }
        __syncthreads();
    }
#pragma unroll
    for (int i = 0; i < 4; i++)
#pragma unroll
        for (int j = 0; j < 2; j++)
            wmma::store_matrix_sync(
                &g_qkv[(size_t)(m0 + wm * 64 + i * 16) * P3D + c0 + wn * 32 + j * 16],
                acc[i][j], P3D, wmma::mem_row_major);
}

// ---------------- prep: scalars + merged scaled operand split ------------
__global__ __launch_bounds__(128) void k_prep2(const float* __restrict__ bias,
                                               const float* __restrict__ tau) {
    int gw = (blockIdx.x * 128 + threadIdx.x) >> 5;
    int lane = threadIdx.x & 31;
    int kind = gw & 3;          // 0:q 1:k 2:vq 3:vk
    int t = gw >> 2;            // (b*8+h)*1024 + n
    int b = t >> 13, h = (t >> 10) & 7, n = t & 1023;
    int row = b * PN + n + ((kind >= 2) ? 4096 : 0);
    int col = ((kind & 1) ? PD : 0) + h * PDH;
    const float* p = g_qkv + (size_t)row * P3D + col;
    float x0 = p[lane] + bias[col + lane];
    float x1 = p[lane + 32] + bias[col + lane + 32];
    float ss = x0 * x0 + x1 * x1;
#pragma unroll
    for (int o = 16; o; o >>= 1) ss += __shfl_xor_sync(~0u, ss, o);
    float tv = fmaxf(tau[h], 1e-3f);
    float scale;
    if (kind < 2) {
        float norm  = sqrtf(fmaxf(ss, 1e-7f));
        float alpha = fminf(3.0f / norm, 1.0f);
        float n2    = sqrtf(fmaxf(ss * alpha * alpha, 1e-14f));
        scale = (sinhf(n2) / n2) * alpha;
        if (kind == 0) {
            scale /= tv;
            if (lane == 0) g_cq[t] = coshf(n2) / tv;     // cosh/tau
        } else {
            if (lane == 0) g_ck[t] = coshf(n2);
        }
    } else {
        scale = 1.4142135623730951f;   // sqrt(2): 2*v.v = (s*vq).(s*vk)
        if (lane == 0) { if (kind == 2) g_vqs[t] = ss; else g_vks[t] = ss; }
    }
    float s0 = scale * x0, s1 = scale * x1;
    __nv_bfloat16 h0 = __float2bfloat16(s0), h1 = __float2bfloat16(s1);
    __nv_bfloat16 l0 = __float2bfloat16(s0 - __bfloat162float(h0));
    __nv_bfloat16 l1 = __float2bfloat16(s1 - __bfloat162float(h1));
    __nv_bfloat16* out = ((kind & 1) ? g_sb : g_sa) + (size_t)t * 256;
    int seg = (kind >= 2) ? 64 : 0;
    out[seg + lane] = h0; out[seg + 32 + lane] = h1;
    out[128 + seg + lane] = l0; out[128 + seg + 32 + lane] = l1;
}

// ---------------- v_s transpose + split (adds bias) ----------------
__global__ __launch_bounds__(256) void k_vhat(const float* __restrict__ bias) {
    __shared__ float tile[64][65];
    const int bh = blockIdx.y, j0 = blockIdx.x * 64;
    const int b = bh >> 3, h = bh & 7;
    const int tid = threadIdx.x;
#pragma unroll
    for (int i = 0; i < 4; i++) {
        int lin = tid + i * 256;
        int r = lin >> 4, c4 = (lin & 15) * 4;
        int col = 1024 + h * PDH + c4;
        float4 v = *reinterpret_cast<const float4*>(
            &g_qkv[(size_t)(b * PN + j0 + r) * P3D + col]);
        tile[r][c4]   = v.x + bias[col];
        tile[r][c4+1] = v.y + bias[col+1];
        tile[r][c4+2] = v.z + bias[col+2];
        tile[r][c4+3] = v.w + bias[col+3];
    }
    __syncthreads();
#pragma unroll
    for (int i = 0; i < 4; i++) {
        int lin = tid + i * 256;
        int d = lin >> 4, jq = (lin & 15) * 4;
        __nv_bfloat16* out = g_vz + (size_t)(bh * PDH + d) * 2048 + j0 + jq;
        unsigned hs[4], ls[4];
#pragma unroll
        for (int k = 0; k < 4; k++) {
            float x = tile[jq + k][d];
            __nv_bfloat16 hb = __float2bfloat16(x);
            __nv_bfloat16 lb = __float2bfloat16(x - __bfloat162float(hb));
            hs[k] = (unsigned)__bfloat16_as_ushort(hb);
            ls[k] = (unsigned)__bfloat16_as_ushort(lb);
        }
        uint2 hh; hh.x = hs[0] | (hs[1] << 16); hh.y = hs[2] | (hs[3] << 16);
        uint2 ll; ll.x = ls[0] | (ls[1] << 16); ll.y = ls[2] | (ls[3] << 16);
        *reinterpret_cast<uint2*>(out) = hh;
        *reinterpret_cast<uint2*>(out + 1024) = ll;
    }
}

// ---------------- topology: boolean bitset powers ----------------
__global__ void k_pack(const float* __restrict__ topo_bias) {
    int i = blockIdx.x, j = threadIdx.x;
    unsigned m = __ballot_sync(~0u, topo_bias[(size_t)i * PN + j] > 0.0f);
    if ((j & 31) == 0) g_bits1[i * 32 + (j >> 5)] = m;
}
__global__ __launch_bounds__(256) void k_sq2() {
    int i = blockIdx.x * 8 + (threadIdx.x >> 5), lane = threadIdx.x & 31;
    unsigned acc = 0;
    for (int w = 0; w < 32; w++) {
        unsigned aw = g_bits1[i * 32 + w];
        while (aw) { int bp = __ffs(aw) - 1; aw &= aw - 1; acc |= g_bits1[(w*32+bp)*32 + lane]; }
    }
    g_bits2[i * 32 + lane] = acc;
}
__global__ __launch_bounds__(256) void k_sq3() {
    int i = blockIdx.x * 8 + (threadIdx.x >> 5), lane = threadIdx.x & 31;
    unsigned acc = 0;
    for (int w = 0; w < 32; w++) {
        unsigned aw = g_bits2[i * 32 + w];
        while (aw) { int bp = __ffs(aw) - 1; aw &= aw - 1; acc |= g_bits1[(w*32+bp)*32 + lane]; }
    }
    g_bits3[i * 32 + lane] = acc;
}
__global__ void k_byte() {
    int i = blockIdx.x, j = threadIdx.x;
    int w = j >> 5, bp = j & 31;
    unsigned char v = 0;
    if (i != j)
        v = (unsigned char)(((g_bits1[i*32+w] >> bp) & 1) |
                            (((g_bits2[i*32+w] >> bp) & 1) << 1) |
                            (((g_bits3[i*32+w] >> bp) & 1) << 2));
    g_topo[(size_t)i * PN + j] = v;
}

// ---------------- T2: merged score GEMM (K=128) + fused epilogue ---------
__global__ __launch_bounds__(256)
void t_scores(const float* __restrict__ tau, const float* __restrict__ gamma,
              float* __restrict__ attn) {
    extern __shared__ __align__(16) uint8_t dsm[];
    __nv_bfloat16* As = (__nv_bfloat16*)dsm;            // 64 x 264 (256 used)
    __nv_bfloat16* Bs = (__nv_bfloat16*)(dsm + 33792);  // 128 x 264
    float* Sqk = (float*)dsm;                           // 64 x 132 (reuses As)
    __shared__ float s_lut[8];

    const int j0 = blockIdx.x * 128, i0 = blockIdx.y * 64, bh = blockIdx.z;
    const int h = bh & 7;
    const int tid = threadIdx.x;
    const int wid = tid >> 5;
    const int wm = wid >> 2, wn = wid & 3;   // warp tile 32 x 32

    if (tid < 8) {
        float g0 = gamma[h*3+0], g1 = gamma[h*3+1], g2 = gamma[h*3+2];
        s_lut[tid] = g0 * (float)(tid & 1) + g1 * (float)((tid >> 1) & 1)
                   + g2 * (float)((tid >> 2) & 1);
    }
    const __nv_bfloat16* asrc = g_sa + (size_t)(bh * PN + i0) * 256;
    const __nv_bfloat16* bsrc = g_sb + (size_t)(bh * PN + j0) * 256;
#pragma unroll
    for (int t = 0; t < 8; t++) {            // A: 64 rows x 32 uint4
        int u = tid + t * 256;
        int r = u >> 5, c8 = (u & 31) * 8;
        *(uint4*)&As[r * 264 + c8] = *(const uint4*)&asrc[(size_t)r * 256 + c8];
    }
#pragma unroll
    for (int t = 0; t < 16; t++) {           // B: 128 rows x 32 uint4
        int u = tid + t * 256;
        int r = u >> 5, c8 = (u & 31) * 8;
        *(uint4*)&Bs[r * 264 + c8] = *(const uint4*)&bsrc[(size_t)r * 256 + c8];
    }
    __syncthreads();

    FragC acc[2][2];
#pragma unroll
    for (int i = 0; i < 2; i++)
#pragma unroll
        for (int j = 0; j < 2; j++) wmma::fill_fragment(acc[i][j], 0.f);

#pragma unroll
    for (int kk = 0; kk < 128; kk += 16) {
        FragB fbh[2], fbl[2];
#pragma unroll
        for (int j = 0; j < 2; j++) {
            wmma::load_matrix_sync(fbh[j], &Bs[(wn * 32 + j * 16) * 264 + kk], 264);
            wmma::load_matrix_sync(fbl[j], &Bs[(wn * 32 + j * 16) * 264 + 128 + kk], 264);
        }
#pragma unroll
        for (int i = 0; i < 2; i++) {
            FragA fah, fal;
            wmma::load_matrix_sync(fah, &As[(wm * 32 + i * 16) * 264 + kk], 264);
            wmma::load_matrix_sync(fal, &As[(wm * 32 + i * 16) * 264 + 128 + kk], 264);
#pragma unroll
            for (int j = 0; j < 2; j++) {
                wmma::mma_sync(acc[i][j], fah, fbh[j], acc[i][j]);
                wmma::mma_sync(acc[i][j], fal, fbh[j], acc[i][j]);
                wmma::mma_sync(acc[i][j], fah, fbl[j], acc[i][j]);
            }
        }
    }
    __syncthreads();   // done with As before overwrite
#pragma unroll
    for (int i = 0; i < 2; i++)
#pragma unroll
        for (int j = 0; j < 2; j++)
            wmma::store_matrix_sync(&Sqk[(wm * 32 + i * 16) * 132 + wn * 32 + j * 16],
                                    acc[i][j], 132, wmma::mem_row_major);
    __syncthreads();

    const int r = tid >> 2;               // 0..63
    const int ce = (tid & 3) * 32;        // 0..96
    const int i = i0 + r;
    const float c0 = 1.0f / fmaxf(tau[h], 1e-3f);
    const float cqi = g_cq[bh * PN + i];   // cosh/tau
    const float vqi = g_vqs[bh * PN + i];
    float* op = attn + (size_t)(bh * PN + i) * PN + j0;
#pragma unroll
    for (int c = ce; c < ce + 32; c += 4) {
        float4 q4 = *(float4*)&Sqk[r * 132 + c];
        float4 ck4 = *(const float4*)&g_ck[bh * PN + j0 + c];
        float4 vk4 = *(const float4*)&g_vks[bh * PN + j0 + c];
        uchar4 tb = *(const uchar4*)&g_topo[(size_t)i * PN + j0 + c];
        float4 s;
        s.x = c0 + q4.x - cqi * ck4.x - vqi - vk4.x + s_lut[tb.x & 7];
        s.y = c0 + q4.y - cqi * ck4.y - vqi - vk4.y + s_lut[tb.y & 7];
        s.z = c0 + q4.z - cqi * ck4.z - vqi - vk4.z + s_lut[tb.z & 7];
        s.w = c0 + q4.w - cqi * ck4.w - vqi - vk4.w + s_lut[tb.w & 7];
        *(float4*)&op[c] = s;
    }
}

// ---------------- softmax + attn hi/lo split ----------------
__global__ __launch_bounds__(256)
void k_softmax_split(float* __restrict__ attn) {
    __shared__ float red[8];
    const size_t row = blockIdx.x;
    float* p = attn + row * PN;
    const int t = threadIdx.x;
    float4 v = *reinterpret_cast<float4*>(&p[t * 4]);
    float m = fmaxf(fmaxf(v.x, v.y), fmaxf(v.z, v.w));
#pragma unroll
    for (int o = 16; o; o >>= 1) m = fmaxf(m, __shfl_xor_sync(~0u, m, o));
    if ((t & 31) == 0) red[t >> 5] = m;
    __syncthreads();
    float mm = red[0];
#pragma unroll
    for (int i = 1; i < 8; i++) mm = fmaxf(mm, red[i]);
    __syncthreads();
    v.x = __expf(v.x - mm); v.y = __expf(v.y - mm);
    v.z = __expf(v.z - mm); v.w = __expf(v.w - mm);
    float s = v.x + v.y + v.z + v.w;
#pragma unroll
    for (int o = 16; o; o >>= 1) s += __shfl_xor_sync(~0u, s, o);
    if ((t & 31) == 0) red[t >> 5] = s;
    __syncthreads();
    float ss = 0.f;
#pragma unroll
    for (int i = 0; i < 8; i++) ss += red[i];
    float inv = 1.0f / ss;
    v.x *= inv; v.y *= inv; v.z *= inv; v.w *= inv;
    *reinterpret_cast<float4*>(&p[t * 4]) = v;
    float vv[4] = {v.x, v.y, v.z, v.w};
    unsigned hs[4], ls[4];
#pragma unroll
    for (int k = 0; k < 4; k++) {
        __nv_bfloat16 hb = __float2bfloat16(vv[k]);
        __nv_bfloat16 lb = __float2bfloat16(vv[k] - __bfloat162float(hb));
        hs[k] = (unsigned)__bfloat16_as_ushort(hb);
        ls[k] = (unsigned)__bfloat16_as_ushort(lb);
    }
    uint2 hh; hh.x = hs[0] | (hs[1] << 16); hh.y = hs[2] | (hs[3] << 16);
    uint2 ll; ll.x = ls[0] | (ls[1] << 16); ll.y = ls[2] | (ls[3] << 16);
    __nv_bfloat16* o = g_asp + row * 2048 + t * 4;
    *reinterpret_cast<uint2*>(o) = hh;
    *reinterpret_cast<uint2*>(o + 1024) = ll;
}

// ---------------- T3: z = attn @ v_s (pipelined, 3-term) -----------------
__global__ __launch_bounds__(256)
void t_zgemm(float* __restrict__ zout) {
    extern __shared__ __align__(16) uint8_t dsm[];
    const int i0 = blockIdx.x * 128, bh = blockIdx.y;
    const int b = bh >> 3, h = bh & 7;
    const int tid = threadIdx.x;
    const int wid = tid >> 5;
    const int wm = wid >> 1, wn = wid & 1;    // warp tile 32 x 32

    FragC acc[2][2];
#pragma unroll
    for (int i = 0; i < 2; i++)
#pragma unroll
        for (int j = 0; j < 2; j++) wmma::fill_fragment(acc[i][j], 0.f);

    const __nv_bfloat16* abase = g_asp + (size_t)(bh * PN + i0) * 2048;
    const __nv_bfloat16* bbase = g_vz + (size_t)(bh * PDH) * 2048;

    auto sbuf = [&](int st, int w) -> __nv_bfloat16* {
        static const int offs[4] = {0, 10240, 20480, 25600};
        return (__nv_bfloat16*)(dsm + st * 30720 + offs[w]);
    };
    auto loadstage = [&](int st, int k0) {
        __nv_bfloat16 *Ah = sbuf(st, 0), *Al = sbuf(st, 1), *Bh = sbuf(st, 2), *Bl = sbuf(st, 3);
#pragma unroll
        for (int t = 0; t < 2; t++) {
            int u = tid + t * 256;
            int r = u >> 2, c8 = (u & 3) * 8;
            cpa16(&Ah[r * 40 + c8], &abase[(size_t)r * 2048 + k0 + c8]);
            cpa16(&Al[r * 40 + c8], &abase[(size_t)r * 2048 + 1024 + k0 + c8]);
        }
        {
            int r = tid >> 2, c8 = (tid & 3) * 8;
            cpa16(&Bh[r * 40 + c8], &bbase[(size_t)r * 2048 + k0 + c8]);
            cpa16(&Bl[r * 40 + c8], &bbase[(size_t)r * 2048 + 1024 + k0 + c8]);
        }
    };

    loadstage(0, 0); CP_COMMIT();
#pragma unroll 1
    for (int ch = 0; ch < 32; ++ch) {
        if (ch < 31) { loadstage((ch + 1) & 1, (ch + 1) * 32); CP_COMMIT(); CP_WAIT1(); }
        else CP_WAIT0();
        __syncthreads();
        __nv_bfloat16 *Ah = sbuf(ch & 1, 0), *Al = sbuf(ch & 1, 1),
                      *Bh = sbuf(ch & 1, 2), *Bl = sbuf(ch & 1, 3);
#pragma unroll
        for (int kk = 0; kk < 32; kk += 16) {
            FragB fbh[2], fbl[2];
#pragma unroll
            for (int j = 0; j < 2; j++) {
                wmma::load_matrix_sync(fbh[j], &Bh[(wn * 32 + j * 16) * 40 + kk], 40);
                wmma::load_matrix_sync(fbl[j], &Bl[(wn * 32 + j * 16) * 40 + kk], 40);
            }
#pragma unroll
            for (int i = 0; i < 2; i++) {
                FragA fah, fal;
                wmma::load_matrix_sync(fah, &Ah[(wm * 32 + i * 16) * 40 + kk], 40);
                wmma::load_matrix_sync(fal, &Al[(wm * 32 + i * 16) * 40 + kk], 40);
#pragma unroll
                for (int j = 0; j < 2; j++) {
                    wmma::mma_sync(acc[i][j], fah, fbh[j], acc[i][j]);
                    wmma::mma_sync(acc[i][j], fal, fbh[j], acc[i][j]);
                    wmma::mma_sync(acc[i][j], fah, fbl[j], acc[i][j]);
                }
            }
        }
        __syncthreads();
    }
#pragma unroll
    for (int i = 0; i < 2; i++)
#pragma unroll
        for (int j = 0; j < 2; j++)
            wmma::store_matrix_sync(
                &zout[(size_t)(b * PN + i0 + wm * 32 + i * 16) * PD + h * PDH + wn * 32 + j * 16],
                acc[i][j], PD, wmma::mem_row_major);
}

// ---------------- launch ----------------
extern "C" void kernel_launch(void* const* d_in, const int* in_sizes, int n_in,
                              void* d_out, int out_size) {
    const float* x     = (const float*)d_in[0];
    const float* v     = (const float*)d_in[1];
    const float* topo  = (const float*)d_in[2];
    const float* w     = (const float*)d_in[3];
    const float* bias  = (const float*)d_in[4];
    const float* tau   = (const float*)d_in[5];
    const float* gamma = (const float*)d_in[6];

    float* out  = (float*)d_out;
    float* z    = out;
    float* attn = out + ZSZ;

    cudaFuncSetAttribute(t_proj,   cudaFuncAttributeMaxDynamicSharedMemorySize, 81920);
    cudaFuncSetAttribute(t_scores, cudaFuncAttributeMaxDynamicSharedMemorySize, 101376);
    cudaFuncSetAttribute(t_zgemm,  cudaFuncAttributeMaxDynamicSharedMemorySize, 61440);

    k_cvt_pa<<<16384, 256>>>(x, v);
    k_cvt_pw<<<3072, 256>>>(w);
    t_proj<<<dim3(12, 64), 256, 81920>>>();
    k_prep2<<<32768, 128>>>(bias, tau);
    k_vhat<<<dim3(16, 32), 256>>>(bias);
    k_pack<<<PN, PN>>>(topo);
    k_sq2<<<128, 256>>>();
    k_sq3<<<128, 256>>>();
    k_byte<<<PN, PN>>>();
    t_scores<<<dim3(8, 16, 32), 256, 101376>>>(tau, gamma, attn);
    k_softmax_split<<<PB * PH * PN, 256>>>(attn);
    t_zgemm<<<dim3(8, 32), 256, 61440>>>(z);
}